// round 1
// baseline (speedup 1.0000x reference)
#include <cuda_runtime.h>
#include <math.h>
#include <stdint.h>

// ---------------- problem constants ----------------
#define N_ROWS 16384
#define D2     1024
#define KSYM   8192
#define KCH    4
#define KCHUNK (KSYM / KCH)   // 2048 cols per chunk
#define BM 64
#define BN 64
#define BK 16
#define MARGIN 0.05f

// output packing (reference tuple order, flattened, float32):
// z_q_st [N*1024], loss [1], min_indices [N], new_codebook [K*1024],
// new_cluster_size [K], new_embed_avg [K*1024]
#define ZQ_OFF   0ULL
#define LOSS_OFF 16777216ULL
#define MIDX_OFF 16777217ULL
#define NCB_OFF  16793601ULL
#define NCS_OFF  25182209ULL
#define NEA_OFF  25190401ULL

// ---------------- scratch (device globals, no allocation) ----------------
__device__ float  g_cnorm[KSYM];
__device__ float  g_top2v[N_ROWS * KCH * 2];
__device__ int    g_top2i[N_ROWS * KCH * 2];
__device__ int    g_midx[N_ROWS];
__device__ int    g_counts[KSYM];
__device__ double g_loss;
__device__ float  g_cs[KSYM];

__device__ __forceinline__ float tanh_approx(float x) {
    float y;
    asm("tanh.approx.f32 %0, %1;" : "=f"(y) : "f"(x));
    return y;
}

// ---------------- 1. codebook row norms (fp64 accumulate -> fp32) ----------------
__global__ void prep_cnorm_kernel(const float* __restrict__ codebook) {
    int k = blockIdx.x;
    const float* row = codebook + (size_t)k * D2;
    double s = 0.0;
    for (int t = threadIdx.x; t < D2; t += 256) {
        double v = (double)row[t];
        s += v * v;
    }
    __shared__ double sh[256];
    sh[threadIdx.x] = s;
    __syncthreads();
    for (int o = 128; o > 0; o >>= 1) {
        if (threadIdx.x < o) sh[threadIdx.x] += sh[threadIdx.x + o];
        __syncthreads();
    }
    if (threadIdx.x == 0) g_cnorm[k] = (float)sh[0];
}

// ---------------- 2. init: new_embed_avg = 0.99*embed_avg, zero counts/loss ----------------
__global__ void init_kernel(const float* __restrict__ embed_avg, float* __restrict__ out) {
    size_t total = (size_t)KSYM * D2;
    size_t stride = (size_t)gridDim.x * blockDim.x;
    size_t j = (size_t)blockIdx.x * blockDim.x + threadIdx.x;
    for (size_t i = j; i < total; i += stride)
        out[NEA_OFF + i] = 0.99f * embed_avg[i];
    if (j < KSYM) g_counts[j] = 0;
    if (j == 0) g_loss = 0.0;
}

// ---------------- 3. fused distance+gate GEMM with per-row top-2 ----------------
__global__ __launch_bounds__(256)
void score_kernel(const float* __restrict__ z_real,  const float* __restrict__ z_imag,
                  const float* __restrict__ ctx_real, const float* __restrict__ ctx_imag,
                  const int*   __restrict__ prev_idx,
                  const float* __restrict__ codebook, const float* __restrict__ adjacency,
                  const float* __restrict__ gate_w,   const float* __restrict__ gate_b) {
    __shared__ float As[BM][BK];    // z tile
    __shared__ float Cs[BM][BK];    // ctx tile
    __shared__ float Bc[BK][BN];    // codebook tile (transposed)
    __shared__ float Bw[BK][BN];    // gate_w tile (transposed)
    __shared__ int   prevs[BM];
    __shared__ float redv[BM][32];
    __shared__ int   redi[BM][32];

    const int tid = threadIdx.x;
    const int tx = tid & 15;        // 16 col-threads
    const int ty = tid >> 4;        // 16 row-threads
    const int rowBase   = blockIdx.x * BM;
    const int chunkBase = blockIdx.y * KCHUNK;

    if (tid < BM) prevs[tid] = prev_idx[rowBase + tid];

    const float INF = __int_as_float(0x7f800000);
    float v1[4], v2[4];
    int   i1[4], i2[4];
#pragma unroll
    for (int i = 0; i < 4; i++) { v1[i] = INF; v2[i] = INF; i1[i] = 0x7fffffff; i2[i] = 0x7fffffff; }

    const int lrow = tid >> 2;          // 0..63
    const int lk4  = (tid & 3) << 2;    // 0,4,8,12

    for (int ct = 0; ct < KCHUNK / BN; ++ct) {
        const int cbase = chunkBase + ct * BN;
        float accd[4][4], accg[4][4];
#pragma unroll
        for (int i = 0; i < 4; i++)
#pragma unroll
            for (int j = 0; j < 4; j++) { accd[i][j] = 0.f; accg[i][j] = 0.f; }

        for (int k0 = 0; k0 < D2; k0 += BK) {
            const float* zsrc; const float* csrc; int koff;
            if (k0 < 512) { zsrc = z_real; csrc = ctx_real; koff = k0; }
            else          { zsrc = z_imag; csrc = ctx_imag; koff = k0 - 512; }
            float4 a4 = *(const float4*)(zsrc + (size_t)(rowBase + lrow) * 512 + koff + lk4);
            float4 c4 = *(const float4*)(csrc + (size_t)(rowBase + lrow) * 512 + koff + lk4);
            *(float4*)&As[lrow][lk4] = a4;
            *(float4*)&Cs[lrow][lk4] = c4;
            float4 b4 = *(const float4*)(codebook + (size_t)(cbase + lrow) * D2 + k0 + lk4);
            float4 w4 = *(const float4*)(gate_w   + (size_t)(cbase + lrow) * D2 + k0 + lk4);
            Bc[lk4 + 0][lrow] = b4.x; Bc[lk4 + 1][lrow] = b4.y;
            Bc[lk4 + 2][lrow] = b4.z; Bc[lk4 + 3][lrow] = b4.w;
            Bw[lk4 + 0][lrow] = w4.x; Bw[lk4 + 1][lrow] = w4.y;
            Bw[lk4 + 2][lrow] = w4.z; Bw[lk4 + 3][lrow] = w4.w;
            __syncthreads();

#pragma unroll
            for (int kk = 0; kk < BK; ++kk) {
                float az[4], ac[4];
#pragma unroll
                for (int i = 0; i < 4; i++) {
                    az[i] = As[ty * 4 + i][kk];
                    ac[i] = Cs[ty * 4 + i][kk];
                }
                float4 bz = *(const float4*)&Bc[kk][tx * 4];
                float4 bw = *(const float4*)&Bw[kk][tx * 4];
                float bza[4] = {bz.x, bz.y, bz.z, bz.w};
                float bwa[4] = {bw.x, bw.y, bw.z, bw.w};
#pragma unroll
                for (int i = 0; i < 4; i++)
#pragma unroll
                    for (int j = 0; j < 4; j++) {
                        accd[i][j] = fmaf(az[i], bza[j], accd[i][j]);
                        accg[i][j] = fmaf(ac[i], bwa[j], accg[i][j]);
                    }
            }
            __syncthreads();
        }

        // epilogue: bias + top-2 update
        const int c0 = cbase + tx * 4;
        float4 cn4 = *(const float4*)(g_cnorm + c0);
        float4 gb4 = *(const float4*)(gate_b + c0);
        float cna[4] = {cn4.x, cn4.y, cn4.z, cn4.w};
        float gba[4] = {gb4.x, gb4.y, gb4.z, gb4.w};
#pragma unroll
        for (int i = 0; i < 4; i++) {
            int pr = prevs[ty * 4 + i];
            float4 ad4 = *(const float4*)(adjacency + (size_t)pr * KSYM + c0);
            float ada[4] = {ad4.x, ad4.y, ad4.z, ad4.w};
#pragma unroll
            for (int j = 0; j < 4; j++) {
                float sig = 1.f / (1.f + __expf(-ada[j]));
                float th  = tanh_approx(accg[i][j] + gba[j]);
                float s = fmaf(-2.f, accd[i][j], cna[j]) - 0.8f * sig * (1.f + 0.5f * th);
                int col = c0 + j;
                if (s < v1[i] || (s == v1[i] && col < i1[i])) {
                    v2[i] = v1[i]; i2[i] = i1[i]; v1[i] = s; i1[i] = col;
                } else if (s < v2[i] || (s == v2[i] && col < i2[i])) {
                    v2[i] = s; i2[i] = col;
                }
            }
        }
    }

    // cross-thread top-2 reduction per row
#pragma unroll
    for (int i = 0; i < 4; i++) {
        redv[ty * 4 + i][tx * 2]     = v1[i]; redi[ty * 4 + i][tx * 2]     = i1[i];
        redv[ty * 4 + i][tx * 2 + 1] = v2[i]; redi[ty * 4 + i][tx * 2 + 1] = i2[i];
    }
    __syncthreads();
    if (tid < BM) {
        float bv1 = INF, bv2 = INF;
        int bi1 = 0x7fffffff, bi2 = 0x7fffffff;
        for (int e = 0; e < 32; e++) {
            float v = redv[tid][e]; int ix = redi[tid][e];
            if (v < bv1 || (v == bv1 && ix < bi1)) { bv2 = bv1; bi2 = bi1; bv1 = v; bi1 = ix; }
            else if (v < bv2 || (v == bv2 && ix < bi2)) { bv2 = v; bi2 = ix; }
        }
        int rg = rowBase + tid;
        size_t o = ((size_t)rg * KCH + blockIdx.y) * 2;
        g_top2v[o] = bv1; g_top2i[o] = bi1;
        g_top2v[o + 1] = bv2; g_top2i[o + 1] = bi2;
    }
}

// ---------------- 4. merge chunk top-2s; fp64 refinement for near-ties ----------------
__global__ void merge_refine_kernel(const float* __restrict__ z_real,  const float* __restrict__ z_imag,
                                    const float* __restrict__ ctx_real, const float* __restrict__ ctx_imag,
                                    const int*   __restrict__ prev_idx,
                                    const float* __restrict__ codebook, const float* __restrict__ adjacency,
                                    const float* __restrict__ gate_w,   const float* __restrict__ gate_b,
                                    float* __restrict__ out) {
    int gwarp = (blockIdx.x * blockDim.x + threadIdx.x) >> 5;
    int lane = threadIdx.x & 31;
    if (gwarp >= N_ROWS) return;
    const int n = gwarp;
    const float INF = __int_as_float(0x7f800000);

    float bv1 = INF, bv2 = INF;
    int bi1 = 0x7fffffff, bi2 = 0x7fffffff;
    if (lane == 0) {
        for (int e = 0; e < KCH * 2; e++) {
            float v = g_top2v[(size_t)n * (KCH * 2) + e];
            int ix  = g_top2i[(size_t)n * (KCH * 2) + e];
            if (v < bv1 || (v == bv1 && ix < bi1)) { bv2 = bv1; bi2 = bi1; bv1 = v; bi1 = ix; }
            else if (v < bv2 || (v == bv2 && ix < bi2)) { bv2 = v; bi2 = ix; }
        }
    }
    bv1 = __shfl_sync(0xffffffffu, bv1, 0);
    bv2 = __shfl_sync(0xffffffffu, bv2, 0);
    bi1 = __shfl_sync(0xffffffffu, bi1, 0);
    bi2 = __shfl_sync(0xffffffffu, bi2, 0);

    int pick = bi1;
    if (bv2 - bv1 < MARGIN) {
        double a0 = 0, a1 = 0, a2 = 0, a3 = 0, a4 = 0, a5 = 0;
        for (int t = lane; t < D2; t += 32) {
            double zt = (t < 512) ? (double)z_real[(size_t)n * 512 + t]
                                  : (double)z_imag[(size_t)n * 512 + t - 512];
            double xt = (t < 512) ? (double)ctx_real[(size_t)n * 512 + t]
                                  : (double)ctx_imag[(size_t)n * 512 + t - 512];
            double c1 = (double)codebook[(size_t)bi1 * D2 + t];
            double w1 = (double)gate_w[(size_t)bi1 * D2 + t];
            double c2 = (double)codebook[(size_t)bi2 * D2 + t];
            double w2 = (double)gate_w[(size_t)bi2 * D2 + t];
            a0 += c1 * c1; a1 += zt * c1; a2 += xt * w1;
            a3 += c2 * c2; a4 += zt * c2; a5 += xt * w2;
        }
        for (int o = 16; o; o >>= 1) {
            a0 += __shfl_down_sync(0xffffffffu, a0, o);
            a1 += __shfl_down_sync(0xffffffffu, a1, o);
            a2 += __shfl_down_sync(0xffffffffu, a2, o);
            a3 += __shfl_down_sync(0xffffffffu, a3, o);
            a4 += __shfl_down_sync(0xffffffffu, a4, o);
            a5 += __shfl_down_sync(0xffffffffu, a5, o);
        }
        if (lane == 0) {
            int p = prev_idx[n];
            double ad1 = (double)adjacency[(size_t)p * KSYM + bi1];
            double ad2 = (double)adjacency[(size_t)p * KSYM + bi2];
            double gb1 = (double)gate_b[bi1];
            double gb2 = (double)gate_b[bi2];
            double d1 = a0 - 2.0 * a1 - 0.8 * (1.0 / (1.0 + exp(-ad1))) * (1.0 + 0.5 * tanh(a2 + gb1));
            double d2 = a3 - 2.0 * a4 - 0.8 * (1.0 / (1.0 + exp(-ad2))) * (1.0 + 0.5 * tanh(a5 + gb2));
            pick = (d2 < d1 || (d2 == d1 && bi2 < bi1)) ? bi2 : bi1;
        }
        pick = __shfl_sync(0xffffffffu, pick, 0);
    }
    if (lane == 0) {
        g_midx[n] = pick;
        out[MIDX_OFF + n] = (float)pick;
        atomicAdd(&g_counts[pick], 1);
    }
}

// ---------------- 5. z_q gather, embed_sum scatter, loss partial ----------------
__global__ void scatter_kernel(const float* __restrict__ z_real, const float* __restrict__ z_imag,
                               const float* __restrict__ codebook, float* __restrict__ out) {
    const int n = blockIdx.x;
    const int m = g_midx[n];
    const int tid = threadIdx.x;
    const int d0 = tid * 4;

    float4 c = *(const float4*)(codebook + (size_t)m * D2 + d0);
    float4 z;
    if (d0 < 512) z = *(const float4*)(z_real + (size_t)n * 512 + d0);
    else          z = *(const float4*)(z_imag + (size_t)n * 512 + d0 - 512);

    *(float4*)(out + ZQ_OFF + (size_t)n * D2 + d0) = c;

    float* ea = out + NEA_OFF + (size_t)m * D2 + d0;
    atomicAdd(ea + 0, 0.01f * z.x);
    atomicAdd(ea + 1, 0.01f * z.y);
    atomicAdd(ea + 2, 0.01f * z.z);
    atomicAdd(ea + 3, 0.01f * z.w);

    float dx = c.x - z.x, dy = c.y - z.y, dz = c.z - z.z, dw = c.w - z.w;
    float lsum = dx * dx + dy * dy + dz * dz + dw * dw;

    __shared__ float sh[256];
    sh[tid] = lsum;
    __syncthreads();
    for (int o = 128; o > 0; o >>= 1) {
        if (tid < o) sh[tid] += sh[tid + o];
        __syncthreads();
    }
    if (tid == 0) atomicAdd(&g_loss, (double)sh[0]);
}

// ---------------- 6a. cluster-size EMA, n_total, cs, loss ----------------
__global__ void finalize_a_kernel(const float* __restrict__ cluster_size, float* __restrict__ out) {
    const int tid = threadIdx.x;  // 1024 threads
    float ncs[8];
    float psum = 0.f;
#pragma unroll
    for (int q = 0; q < 8; q++) {
        int k = tid * 8 + q;
        float v = cluster_size[k] * 0.99f + 0.01f * (float)g_counts[k];
        ncs[q] = v;
        out[NCS_OFF + k] = v;
        psum += v;
    }
    __shared__ float sh[1024];
    sh[tid] = psum;
    __syncthreads();
    for (int o = 512; o > 0; o >>= 1) {
        if (tid < o) sh[tid] += sh[tid + o];
        __syncthreads();
    }
    float ntot = sh[0];
#pragma unroll
    for (int q = 0; q < 8; q++) {
        float cs = (ncs[q] + 1e-6f) / (ntot + (float)KSYM * 1e-6f) * ntot;
        g_cs[tid * 8 + q] = cs;
    }
    if (tid == 0) out[LOSS_OFF] = (float)(1.25 * g_loss / 16777216.0);
}

// ---------------- 6b. new_codebook = new_embed_avg / cs ----------------
__global__ void finalize_b_kernel(float* __restrict__ out) {
    size_t total = (size_t)KSYM * D2;
    size_t stride = (size_t)gridDim.x * blockDim.x;
    for (size_t i = (size_t)blockIdx.x * blockDim.x + threadIdx.x; i < total; i += stride) {
        int k = (int)(i >> 10);
        out[NCB_OFF + i] = out[NEA_OFF + i] / g_cs[k];
    }
}

// ---------------- entry ----------------
extern "C" void kernel_launch(void* const* d_in, const int* in_sizes, int n_in,
                              void* d_out, int out_size) {
    const float* z_real     = (const float*)d_in[0];
    const float* z_imag     = (const float*)d_in[1];
    const float* ctx_real   = (const float*)d_in[2];
    const float* ctx_imag   = (const float*)d_in[3];
    const int*   prev_idx   = (const int*)d_in[4];
    const float* codebook   = (const float*)d_in[5];
    const float* adjacency  = (const float*)d_in[6];
    const float* gate_w     = (const float*)d_in[7];
    const float* gate_b     = (const float*)d_in[8];
    const float* cluster_sz = (const float*)d_in[9];
    const float* embed_avg  = (const float*)d_in[10];
    float* out = (float*)d_out;

    prep_cnorm_kernel<<<KSYM, 256>>>(codebook);
    init_kernel<<<8192, 256>>>(embed_avg, out);
    score_kernel<<<dim3(N_ROWS / BM, KCH), 256>>>(z_real, z_imag, ctx_real, ctx_imag,
                                                  prev_idx, codebook, adjacency, gate_w, gate_b);
    merge_refine_kernel<<<N_ROWS / 8, 256>>>(z_real, z_imag, ctx_real, ctx_imag,
                                             prev_idx, codebook, adjacency, gate_w, gate_b, out);
    scatter_kernel<<<N_ROWS, 256>>>(z_real, z_imag, codebook, out);
    finalize_a_kernel<<<1, 1024>>>(cluster_sz, out);
    finalize_b_kernel<<<8192, 256>>>(out);
}

// round 3
// speedup vs baseline: 5.6368x; 5.6368x over previous
#include <cuda_runtime.h>
#include <math.h>
#include <stdint.h>

// ---------------- problem constants ----------------
#define N_ROWS 16384
#define D2     1024
#define KSYM   8192
#define BM     128            // rows per CTA (blockIdx.y)
#define BN     64             // symbol cols per CTA (blockIdx.x)
#define BK     32             // k-chunk (floats) per stage = 128B/row
#define NCHUNK (D2 / BK)      // 32
#define RECORDS 256           // per-row top2 records = (KSYM/BN) * 2 warpsN
#define MARGIN 0.5f

// output packing (reference tuple order, flattened, float32)
#define ZQ_OFF   0ULL
#define LOSS_OFF 16777216ULL
#define MIDX_OFF 16777217ULL
#define NCB_OFF  16793601ULL
#define NCS_OFF  25182209ULL
#define NEA_OFF  25190401ULL

// smem stage layout
#define SEG_Z   0
#define SEG_C   16384
#define SEG_CB  32768
#define SEG_GW  40960
#define STAGE   49152
#define SMEM_BYTES (2 * STAGE)

// ---------------- scratch (device globals, no allocation) ----------------
__device__ float  g_cnorm[KSYM];
__device__ float  g_top2v[(size_t)N_ROWS * RECORDS * 2];
__device__ int    g_top2i[(size_t)N_ROWS * RECORDS * 2];
__device__ int    g_midx[N_ROWS];
__device__ int    g_counts[KSYM];
__device__ double g_loss;
__device__ float  g_cs[KSYM];

// ---------------- helpers ----------------
__device__ __forceinline__ uint32_t smem_to_u32(const void* p) {
    uint32_t a;
    asm("{ .reg .u64 t; cvta.to.shared.u64 t, %1; cvt.u32.u64 %0, t; }" : "=r"(a) : "l"(p));
    return a;
}
__device__ __forceinline__ float tanh_approx(float x) {
    float y; asm("tanh.approx.f32 %0, %1;" : "=f"(y) : "f"(x)); return y;
}
__device__ __forceinline__ void cp16(uint32_t dst, const void* src) {
    asm volatile("cp.async.cg.shared.global [%0], [%1], 16;" :: "r"(dst), "l"(src));
}
__device__ __forceinline__ uint32_t lds32(uint32_t addr) {
    uint32_t v; asm volatile("ld.shared.b32 %0, [%1];" : "=r"(v) : "r"(addr)); return v;
}
__device__ __forceinline__ void mma_tf32(float* d, const uint32_t* a, const uint32_t* b) {
    asm volatile(
        "mma.sync.aligned.m16n8k8.row.col.f32.tf32.tf32.f32 "
        "{%0,%1,%2,%3}, {%4,%5,%6,%7}, {%8,%9}, {%0,%1,%2,%3};"
        : "+f"(d[0]), "+f"(d[1]), "+f"(d[2]), "+f"(d[3])
        : "r"(a[0]), "r"(a[1]), "r"(a[2]), "r"(a[3]), "r"(b[0]), "r"(b[1]));
}

// ---------------- 1. codebook row norms (fp64 accumulate) ----------------
__global__ void prep_cnorm_kernel(const float* __restrict__ codebook) {
    int k = blockIdx.x;
    const float* row = codebook + (size_t)k * D2;
    double s = 0.0;
    for (int t = threadIdx.x; t < D2; t += 256) { double v = (double)row[t]; s += v * v; }
    __shared__ double sh[256];
    sh[threadIdx.x] = s; __syncthreads();
    for (int o = 128; o > 0; o >>= 1) { if (threadIdx.x < o) sh[threadIdx.x] += sh[threadIdx.x + o]; __syncthreads(); }
    if (threadIdx.x == 0) g_cnorm[k] = (float)sh[0];
}

// ---------------- 2. init ----------------
__global__ void init_kernel(const float* __restrict__ embed_avg, float* __restrict__ out) {
    size_t total = (size_t)KSYM * D2;
    size_t stride = (size_t)gridDim.x * blockDim.x;
    size_t j = (size_t)blockIdx.x * blockDim.x + threadIdx.x;
    for (size_t i = j; i < total; i += stride) out[NEA_OFF + i] = 0.99f * embed_avg[i];
    if (j < KSYM) g_counts[j] = 0;
    if (j == 0) g_loss = 0.0;
}

// ---------------- 3. fused dual-GEMM score kernel (mma.sync tf32) ----------------
__global__ __launch_bounds__(256, 2)
void score_mma_kernel(const float* __restrict__ z_real,  const float* __restrict__ z_imag,
                      const float* __restrict__ ctx_real, const float* __restrict__ ctx_imag,
                      const int*   __restrict__ prev_idx,
                      const float* __restrict__ codebook, const float* __restrict__ adjacency,
                      const float* __restrict__ gate_w,   const float* __restrict__ gate_b) {
    extern __shared__ char smem[];
    const uint32_t sbu = smem_to_u32(smem);
    const int tid   = threadIdx.x;
    const int wid   = tid >> 5;
    const int lane  = tid & 31;
    const int g     = lane >> 2;      // group id 0..7
    const int tig   = lane & 3;       // thread-in-group
    const int warpM = wid >> 1;       // 0..3
    const int warpN = wid & 1;        // 0..1
    const int rowBase = blockIdx.y * BM;
    const int cbase   = blockIdx.x * BN;

    // ---- stage loader: 12 x 16B per thread ----
    auto load_stage = [&](int c, int buf) {
        const int k0 = c * BK;
        const float* zs = (k0 < 512) ? z_real : z_imag;
        const float* xs = (k0 < 512) ? ctx_real : ctx_imag;
        const int ko = k0 & 511;
        const uint32_t bb = sbu + (uint32_t)buf * STAGE;
#pragma unroll
        for (int i = 0; i < 4; i++) {
            int q = tid + (i << 8);
            int r = q >> 3, kq = q & 7;
            uint32_t so = (uint32_t)(r * 128 + ((kq * 16) ^ ((r & 7) << 4)));
            size_t go = (size_t)(rowBase + r) * 512 + ko + kq * 4;
            cp16(bb + SEG_Z + so, zs + go);
            cp16(bb + SEG_C + so, xs + go);
        }
#pragma unroll
        for (int i = 0; i < 2; i++) {
            int q = tid + (i << 8);
            int r = q >> 3, kq = q & 7;
            uint32_t so = (uint32_t)(r * 128 + ((kq * 16) ^ ((r & 7) << 4)));
            size_t go = (size_t)(cbase + r) * 1024 + k0 + kq * 4;
            cp16(bb + SEG_CB + so, codebook + go);
            cp16(bb + SEG_GW + so, gate_w + go);
        }
        asm volatile("cp.async.commit_group;" ::: "memory");
    };

    float accd[2][4][4], accg[2][4][4];
#pragma unroll
    for (int mt = 0; mt < 2; mt++)
#pragma unroll
        for (int nt = 0; nt < 4; nt++)
#pragma unroll
            for (int e = 0; e < 4; e++) { accd[mt][nt][e] = 0.f; accg[mt][nt][e] = 0.f; }

    const uint32_t swm  = (uint32_t)g << 4;
    const uint32_t aoffZ = SEG_Z  + (uint32_t)(warpM * 32 + g) * 128;
    const uint32_t aoffC = SEG_C  + (uint32_t)(warpM * 32 + g) * 128;
    const uint32_t boffB = SEG_CB + (uint32_t)(warpN * 32 + g) * 128;
    const uint32_t boffW = SEG_GW + (uint32_t)(warpN * 32 + g) * 128;

    load_stage(0, 0);

    for (int c = 0; c < NCHUNK; ++c) {
        if (c + 1 < NCHUNK) {
            load_stage(c + 1, (c + 1) & 1);
            asm volatile("cp.async.wait_group 1;" ::: "memory");
        } else {
            asm volatile("cp.async.wait_group 0;" ::: "memory");
        }
        __syncthreads();
        const uint32_t bb = sbu + (uint32_t)(c & 1) * STAGE;

#pragma unroll
        for (int ks = 0; ks < 4; ks++) {
            const uint32_t kb0 = ((uint32_t)(ks * 8 + tig) * 4) ^ swm;
            const uint32_t kb1 = kb0 ^ 16u;
            uint32_t az[2][4], ac[2][4];
#pragma unroll
            for (int mt = 0; mt < 2; mt++) {
                uint32_t ro = bb + aoffZ + (uint32_t)mt * 2048;
                az[mt][0] = lds32(ro + kb0);
                az[mt][1] = lds32(ro + 1024 + kb0);
                az[mt][2] = lds32(ro + kb1);
                az[mt][3] = lds32(ro + 1024 + kb1);
                uint32_t rc = bb + aoffC + (uint32_t)mt * 2048;
                ac[mt][0] = lds32(rc + kb0);
                ac[mt][1] = lds32(rc + 1024 + kb0);
                ac[mt][2] = lds32(rc + kb1);
                ac[mt][3] = lds32(rc + 1024 + kb1);
            }
            uint32_t bc[4][2], bw[4][2];
#pragma unroll
            for (int nt = 0; nt < 4; nt++) {
                uint32_t ro = bb + boffB + (uint32_t)nt * 1024;
                bc[nt][0] = lds32(ro + kb0);
                bc[nt][1] = lds32(ro + kb1);
                uint32_t rw = bb + boffW + (uint32_t)nt * 1024;
                bw[nt][0] = lds32(rw + kb0);
                bw[nt][1] = lds32(rw + kb1);
            }
#pragma unroll
            for (int mt = 0; mt < 2; mt++)
#pragma unroll
                for (int nt = 0; nt < 4; nt++) {
                    mma_tf32(accd[mt][nt], az[mt], bc[nt]);
                    mma_tf32(accg[mt][nt], ac[mt], bw[nt]);
                }
        }
        __syncthreads();
    }

    // ---- epilogue: bias + per-row top-2 ----
    float cnv[4][2], gbv[4][2];
#pragma unroll
    for (int nt = 0; nt < 4; nt++)
#pragma unroll
        for (int e = 0; e < 2; e++) {
            int col = cbase + warpN * 32 + nt * 8 + 2 * tig + e;
            cnv[nt][e] = g_cnorm[col];
            gbv[nt][e] = gate_b[col];
        }

    const float INF = __int_as_float(0x7f800000);
#pragma unroll
    for (int mt = 0; mt < 2; mt++)
#pragma unroll
        for (int hi = 0; hi < 2; hi++) {
            int rowg = rowBase + warpM * 32 + mt * 16 + hi * 8 + g;
            const float* adjr = adjacency + (size_t)prev_idx[rowg] * KSYM;
            float V1 = INF, V2 = INF;
            int   I1 = 0x7fffffff, I2 = 0x7fffffff;
#pragma unroll
            for (int nt = 0; nt < 4; nt++)
#pragma unroll
                for (int e = 0; e < 2; e++) {
                    int col = cbase + warpN * 32 + nt * 8 + 2 * tig + e;
                    float dot = accd[mt][nt][hi * 2 + e];
                    float gt  = accg[mt][nt][hi * 2 + e];
                    float adj = __ldg(adjr + col);
                    float sig = 1.f / (1.f + __expf(-adj));
                    float th  = tanh_approx(gt + gbv[nt][e]);
                    float s = fmaf(-2.f, dot, cnv[nt][e]) - 0.8f * sig * fmaf(0.5f, th, 1.f);
                    if (s < V1 || (s == V1 && col < I1)) { V2 = V1; I2 = I1; V1 = s; I1 = col; }
                    else if (s < V2 || (s == V2 && col < I2)) { V2 = s; I2 = col; }
                }
            // merge top-2 across the 4 lanes of the row group
#pragma unroll
            for (int off = 1; off <= 2; off <<= 1) {
                float ov1 = __shfl_xor_sync(0xffffffffu, V1, off);
                int   oi1 = __shfl_xor_sync(0xffffffffu, I1, off);
                float ov2 = __shfl_xor_sync(0xffffffffu, V2, off);
                int   oi2 = __shfl_xor_sync(0xffffffffu, I2, off);
                if (ov1 < V1 || (ov1 == V1 && oi1 < I1)) {
                    float nv2; int ni2;
                    if (V1 < ov2 || (V1 == ov2 && I1 < oi2)) { nv2 = V1; ni2 = I1; }
                    else { nv2 = ov2; ni2 = oi2; }
                    V1 = ov1; I1 = oi1; V2 = nv2; I2 = ni2;
                } else if (ov1 < V2 || (ov1 == V2 && oi1 < I2)) {
                    V2 = ov1; I2 = oi1;
                }
            }
            if (tig == 0) {
                size_t o = ((size_t)rowg * RECORDS + blockIdx.x * 2 + warpN) * 2;
                g_top2v[o] = V1;  g_top2i[o] = I1;
                g_top2v[o + 1] = V2; g_top2i[o + 1] = I2;
            }
        }
}

// ---------------- 4. merge top-2s; fp64 refinement for near-ties ----------------
__global__ void merge_refine_kernel(const float* __restrict__ z_real,  const float* __restrict__ z_imag,
                                    const float* __restrict__ ctx_real, const float* __restrict__ ctx_imag,
                                    const int*   __restrict__ prev_idx,
                                    const float* __restrict__ codebook, const float* __restrict__ adjacency,
                                    const float* __restrict__ gate_w,   const float* __restrict__ gate_b,
                                    float* __restrict__ out) {
    int gwarp = (blockIdx.x * blockDim.x + threadIdx.x) >> 5;
    int lane = threadIdx.x & 31;
    if (gwarp >= N_ROWS) return;
    const int n = gwarp;
    const float INF = __int_as_float(0x7f800000);

    float v1 = INF, v2 = INF;
    int i1 = 0x7fffffff, i2 = 0x7fffffff;
    const size_t base = (size_t)n * (RECORDS * 2);
#pragma unroll
    for (int q = 0; q < 16; q++) {
        int e = lane + q * 32;
        float v = g_top2v[base + e];
        int ix  = g_top2i[base + e];
        if (v < v1 || (v == v1 && ix < i1)) { v2 = v1; i2 = i1; v1 = v; i1 = ix; }
        else if (v < v2 || (v == v2 && ix < i2)) { v2 = v; i2 = ix; }
    }
#pragma unroll
    for (int off = 16; off; off >>= 1) {
        float ov1 = __shfl_down_sync(0xffffffffu, v1, off);
        float ov2 = __shfl_down_sync(0xffffffffu, v2, off);
        int   oi1 = __shfl_down_sync(0xffffffffu, i1, off);
        int   oi2 = __shfl_down_sync(0xffffffffu, i2, off);
        if (ov1 < v1 || (ov1 == v1 && oi1 < i1)) { v2 = v1; i2 = i1; v1 = ov1; i1 = oi1; }
        else if (ov1 < v2 || (ov1 == v2 && oi1 < i2)) { v2 = ov1; i2 = oi1; }
        if (ov2 < v1 || (ov2 == v1 && oi2 < i1)) { v2 = v1; i2 = i1; v1 = ov2; i1 = oi2; }
        else if (ov2 < v2 || (ov2 == v2 && oi2 < i2)) { v2 = ov2; i2 = oi2; }
    }
    float bv1 = __shfl_sync(0xffffffffu, v1, 0);
    float bv2 = __shfl_sync(0xffffffffu, v2, 0);
    int   bi1 = __shfl_sync(0xffffffffu, i1, 0);
    int   bi2 = __shfl_sync(0xffffffffu, i2, 0);

    int pick = bi1;
    if (bv2 - bv1 < MARGIN) {
        double a0 = 0, a1 = 0, a2 = 0, a3 = 0, a4 = 0, a5 = 0;
        for (int t = lane; t < D2; t += 32) {
            double zt = (t < 512) ? (double)z_real[(size_t)n * 512 + t]
                                  : (double)z_imag[(size_t)n * 512 + t - 512];
            double xt = (t < 512) ? (double)ctx_real[(size_t)n * 512 + t]
                                  : (double)ctx_imag[(size_t)n * 512 + t - 512];
            double c1 = (double)codebook[(size_t)bi1 * D2 + t];
            double w1 = (double)gate_w[(size_t)bi1 * D2 + t];
            double c2 = (double)codebook[(size_t)bi2 * D2 + t];
            double w2 = (double)gate_w[(size_t)bi2 * D2 + t];
            a0 += c1 * c1; a1 += zt * c1; a2 += xt * w1;
            a3 += c2 * c2; a4 += zt * c2; a5 += xt * w2;
        }
        for (int o = 16; o; o >>= 1) {
            a0 += __shfl_down_sync(0xffffffffu, a0, o);
            a1 += __shfl_down_sync(0xffffffffu, a1, o);
            a2 += __shfl_down_sync(0xffffffffu, a2, o);
            a3 += __shfl_down_sync(0xffffffffu, a3, o);
            a4 += __shfl_down_sync(0xffffffffu, a4, o);
            a5 += __shfl_down_sync(0xffffffffu, a5, o);
        }
        if (lane == 0) {
            int p = prev_idx[n];
            double ad1 = (double)adjacency[(size_t)p * KSYM + bi1];
            double ad2 = (double)adjacency[(size_t)p * KSYM + bi2];
            double gb1 = (double)gate_b[bi1];
            double gb2 = (double)gate_b[bi2];
            double d1 = a0 - 2.0 * a1 - 0.8 * (1.0 / (1.0 + exp(-ad1))) * (1.0 + 0.5 * tanh(a2 + gb1));
            double d2 = a3 - 2.0 * a4 - 0.8 * (1.0 / (1.0 + exp(-ad2))) * (1.0 + 0.5 * tanh(a5 + gb2));
            pick = (d2 < d1 || (d2 == d1 && bi2 < bi1)) ? bi2 : bi1;
        }
        pick = __shfl_sync(0xffffffffu, pick, 0);
    }
    if (lane == 0) {
        g_midx[n] = pick;
        out[MIDX_OFF + n] = (float)pick;
        atomicAdd(&g_counts[pick], 1);
    }
}

// ---------------- 5. z_q gather, embed_sum scatter, loss ----------------
__global__ void scatter_kernel(const float* __restrict__ z_real, const float* __restrict__ z_imag,
                               const float* __restrict__ codebook, float* __restrict__ out) {
    const int n = blockIdx.x;
    const int m = g_midx[n];
    const int tid = threadIdx.x;
    const int d0 = tid * 4;

    float4 c = *(const float4*)(codebook + (size_t)m * D2 + d0);
    float4 z;
    if (d0 < 512) z = *(const float4*)(z_real + (size_t)n * 512 + d0);
    else          z = *(const float4*)(z_imag + (size_t)n * 512 + d0 - 512);

    *(float4*)(out + ZQ_OFF + (size_t)n * D2 + d0) = c;

    float* ea = out + NEA_OFF + (size_t)m * D2 + d0;
    atomicAdd(ea + 0, 0.01f * z.x);
    atomicAdd(ea + 1, 0.01f * z.y);
    atomicAdd(ea + 2, 0.01f * z.z);
    atomicAdd(ea + 3, 0.01f * z.w);

    float dx = c.x - z.x, dy = c.y - z.y, dz = c.z - z.z, dw = c.w - z.w;
    float lsum = dx * dx + dy * dy + dz * dz + dw * dw;

    __shared__ float sh[256];
    sh[tid] = lsum; __syncthreads();
    for (int o = 128; o > 0; o >>= 1) { if (tid < o) sh[tid] += sh[tid + o]; __syncthreads(); }
    if (tid == 0) atomicAdd(&g_loss, (double)sh[0]);
}

// ---------------- 6a. cluster-size EMA, cs, loss ----------------
__global__ void finalize_a_kernel(const float* __restrict__ cluster_size, float* __restrict__ out) {
    const int tid = threadIdx.x;  // 1024 threads
    float ncs[8];
    float psum = 0.f;
#pragma unroll
    for (int q = 0; q < 8; q++) {
        int k = tid * 8 + q;
        float v = cluster_size[k] * 0.99f + 0.01f * (float)g_counts[k];
        ncs[q] = v;
        out[NCS_OFF + k] = v;
        psum += v;
    }
    __shared__ float sh[1024];
    sh[tid] = psum; __syncthreads();
    for (int o = 512; o > 0; o >>= 1) { if (tid < o) sh[tid] += sh[tid + o]; __syncthreads(); }
    float ntot = sh[0];
#pragma unroll
    for (int q = 0; q < 8; q++) {
        float cs = (ncs[q] + 1e-6f) / (ntot + (float)KSYM * 1e-6f) * ntot;
        g_cs[tid * 8 + q] = cs;
    }
    if (tid == 0) out[LOSS_OFF] = (float)(1.25 * g_loss / 16777216.0);
}

// ---------------- 6b. new_codebook = new_embed_avg / cs ----------------
__global__ void finalize_b_kernel(float* __restrict__ out) {
    size_t total = (size_t)KSYM * D2;
    size_t stride = (size_t)gridDim.x * blockDim.x;
    for (size_t i = (size_t)blockIdx.x * blockDim.x + threadIdx.x; i < total; i += stride) {
        int k = (int)(i >> 10);
        out[NCB_OFF + i] = out[NEA_OFF + i] / g_cs[k];
    }
}

// ---------------- entry ----------------
extern "C" void kernel_launch(void* const* d_in, const int* in_sizes, int n_in,
                              void* d_out, int out_size) {
    const float* z_real     = (const float*)d_in[0];
    const float* z_imag     = (const float*)d_in[1];
    const float* ctx_real   = (const float*)d_in[2];
    const float* ctx_imag   = (const float*)d_in[3];
    const int*   prev_idx   = (const int*)d_in[4];
    const float* codebook   = (const float*)d_in[5];
    const float* adjacency  = (const float*)d_in[6];
    const float* gate_w     = (const float*)d_in[7];
    const float* gate_b     = (const float*)d_in[8];
    const float* cluster_sz = (const float*)d_in[9];
    const float* embed_avg  = (const float*)d_in[10];
    float* out = (float*)d_out;

    cudaFuncSetAttribute(score_mma_kernel, cudaFuncAttributeMaxDynamicSharedMemorySize, SMEM_BYTES);

    prep_cnorm_kernel<<<KSYM, 256>>>(codebook);
    init_kernel<<<8192, 256>>>(embed_avg, out);
    // blockIdx.x = column tile (fast) so codebook/gate_w stay L2-resident
    score_mma_kernel<<<dim3(KSYM / BN, N_ROWS / BM), 256, SMEM_BYTES>>>(
        z_real, z_imag, ctx_real, ctx_imag, prev_idx, codebook, adjacency, gate_w, gate_b);
    merge_refine_kernel<<<N_ROWS / 8, 256>>>(z_real, z_imag, ctx_real, ctx_imag,
                                             prev_idx, codebook, adjacency, gate_w, gate_b, out);
    scatter_kernel<<<N_ROWS, 256>>>(z_real, z_imag, codebook, out);
    finalize_a_kernel<<<1, 1024>>>(cluster_sz, out);
    finalize_b_kernel<<<8192, 256>>>(out);
}